// round 5
// baseline (speedup 1.0000x reference)
#include <cuda_runtime.h>
#include <cstdint>

// LIF scan: for each (batch, neuron) row of T=100 contiguous fp32 values:
//   v = v*0.5 + x_t; s = (v - 0.5 > 0) ? 1 : 0; v -= s*0.5
// Rows are fully independent -> 1 thread per row, float4 vectorized I/O.

static constexpr int T = 100;          // time steps (contiguous, innermost)
static constexpr int T4 = T / 4;       // 25 float4 per row
static constexpr float DECAY = 0.5f;   // 1 - 1/TAU, TAU=2
static constexpr float V_TH = 0.5f;

__global__ __launch_bounds__(256) void lif_kernel(
    const float* __restrict__ x,
    float* __restrict__ out,
    int rows)
{
    int row = blockIdx.x * blockDim.x + threadIdx.x;
    if (row >= rows) return;

    const float4* __restrict__ xr  = reinterpret_cast<const float4*>(x + (size_t)row * T);
    float4* __restrict__ outr      = reinterpret_cast<float4*>(out + (size_t)row * T);

    float v = 0.0f;
#pragma unroll
    for (int i = 0; i < T4; ++i) {
        float4 xi = xr[i];
        float4 s;

        v = fmaf(v, DECAY, xi.x);
        s.x = (v > V_TH) ? 1.0f : 0.0f;
        v = fmaf(s.x, -V_TH, v);

        v = fmaf(v, DECAY, xi.y);
        s.y = (v > V_TH) ? 1.0f : 0.0f;
        v = fmaf(s.y, -V_TH, v);

        v = fmaf(v, DECAY, xi.z);
        s.z = (v > V_TH) ? 1.0f : 0.0f;
        v = fmaf(s.z, -V_TH, v);

        v = fmaf(v, DECAY, xi.w);
        s.w = (v > V_TH) ? 1.0f : 0.0f;
        v = fmaf(s.w, -V_TH, v);

        outr[i] = s;
    }
}

extern "C" void kernel_launch(void* const* d_in, const int* in_sizes, int n_in,
                              void* d_out, int out_size)
{
    const float* x = (const float*)d_in[0];
    float* out = (float*)d_out;

    int rows = in_sizes[0] / T;   // 32 * 16384 = 524288
    int threads = 256;
    int blocks = (rows + threads - 1) / threads;
    lif_kernel<<<blocks, threads>>>(x, out, rows);
}

// round 7
// speedup vs baseline: 2.3694x; 2.3694x over previous
#include <cuda_runtime.h>
#include <cstdint>

// LIF scan, coalesced via smem staging.
// Layout: x, out are [rows=524288][T=100] fp32, time contiguous.
// Previous kernel (1 thread/row, direct gmem) was L1tex-wavefront bound:
// each LDG.128/STG.128 touched 32 lines (lanes 400B apart). Fix: stage the
// CTA's 64-row tile through smem with coalesced float4 gmem access, scan
// in-place in smem (padded stride 108 floats -> conflict-free LDS/STS.128).

static constexpr int T = 100;
static constexpr int T4 = T / 4;            // 25 float4 per row
static constexpr int ROWS_PER_CTA = 64;     // 1 thread per row in scan phase
static constexpr int SMEM_STRIDE = 108;     // floats; 12*l mod 32 covers all banks
static constexpr float DECAY = 0.5f;        // 1 - 1/TAU, TAU=2
static constexpr float V_TH = 0.5f;

__global__ __launch_bounds__(ROWS_PER_CTA) void lif_kernel(
    const float* __restrict__ x,
    float* __restrict__ out,
    int rows)
{
    __shared__ float tile[ROWS_PER_CTA * SMEM_STRIDE];  // 27648 B

    const int tid = threadIdx.x;
    const int row0 = blockIdx.x * ROWS_PER_CTA;         // first row of tile

    const float4* __restrict__ gsrc =
        reinterpret_cast<const float4*>(x + (size_t)row0 * T);
    float4* __restrict__ gdst =
        reinterpret_cast<float4*>(out + (size_t)row0 * T);

    // ---- Phase 1: coalesced gmem -> smem (float4; rows are 25 float4, no straddle)
    constexpr int F4_PER_TILE = ROWS_PER_CTA * T4;      // 1600
#pragma unroll
    for (int k = 0; k < F4_PER_TILE / ROWS_PER_CTA; ++k) {   // 25 iters
        int fidx = tid + k * ROWS_PER_CTA;
        int r = fidx / T4;
        int c4 = fidx % T4;
        float4 v4 = gsrc[fidx];
        *reinterpret_cast<float4*>(&tile[r * SMEM_STRIDE + c4 * 4]) = v4;
    }
    __syncthreads();

    // ---- Phase 2: per-thread scan over its own smem row, in place
    {
        float* rowp = &tile[tid * SMEM_STRIDE];
        float v = 0.0f;
#pragma unroll
        for (int i = 0; i < T4; ++i) {
            float4 xi = *reinterpret_cast<const float4*>(&rowp[i * 4]);
            float4 s;

            v = fmaf(v, DECAY, xi.x);
            s.x = (v > V_TH) ? 1.0f : 0.0f;
            v = fmaf(s.x, -V_TH, v);

            v = fmaf(v, DECAY, xi.y);
            s.y = (v > V_TH) ? 1.0f : 0.0f;
            v = fmaf(s.y, -V_TH, v);

            v = fmaf(v, DECAY, xi.z);
            s.z = (v > V_TH) ? 1.0f : 0.0f;
            v = fmaf(s.z, -V_TH, v);

            v = fmaf(v, DECAY, xi.w);
            s.w = (v > V_TH) ? 1.0f : 0.0f;
            v = fmaf(s.w, -V_TH, v);

            *reinterpret_cast<float4*>(&rowp[i * 4]) = s;
        }
    }
    __syncthreads();

    // ---- Phase 3: coalesced smem -> gmem
#pragma unroll
    for (int k = 0; k < F4_PER_TILE / ROWS_PER_CTA; ++k) {   // 25 iters
        int fidx = tid + k * ROWS_PER_CTA;
        int r = fidx / T4;
        int c4 = fidx % T4;
        float4 s4 = *reinterpret_cast<const float4*>(&tile[r * SMEM_STRIDE + c4 * 4]);
        gdst[fidx] = s4;
    }
}

extern "C" void kernel_launch(void* const* d_in, const int* in_sizes, int n_in,
                              void* d_out, int out_size)
{
    const float* x = (const float*)d_in[0];
    float* out = (float*)d_out;

    int rows = in_sizes[0] / T;                 // 524288
    int blocks = rows / ROWS_PER_CTA;           // 8192
    lif_kernel<<<blocks, ROWS_PER_CTA>>>(x, out, rows);
}